// round 4
// baseline (speedup 1.0000x reference)
#include <cuda_runtime.h>
#include <cstdint>

#define NN 50000
#define EE 800000
#define DD 128
#define HH 8

// ---------------- scratch (static __device__ arrays; no allocation) ------------
__device__ float g_q[(size_t)NN * DD];
__device__ float g_k[(size_t)NN * DD];
__device__ float g_v[(size_t)NN * DD];
__device__ float g_agg[(size_t)NN * DD];
__device__ float g_logits[(size_t)EE * HH];   // fallback if out buffer lacks logits room
__device__ int   g_dst[EE];
__device__ int   g_src[EE];
__device__ int   g_deg[NN];
__device__ int   g_rowptr[NN + 1];
__device__ int   g_cursor[NN];
__device__ int   g_eids[EE];
__device__ int   g_is64;

// ---------------- f32x2 helpers (FFMA2 only reachable via PTX) -----------------
__device__ __forceinline__ unsigned long long pk2(float v) {
    unsigned u = __float_as_uint(v);
    unsigned long long p;
    asm("mov.b64 %0, {%1, %1};" : "=l"(p) : "r"(u));
    return p;
}
__device__ __forceinline__ void ffma2(unsigned long long& acc, unsigned long long a,
                                      unsigned long long b) {
    asm("fma.rn.f32x2 %0, %1, %2, %0;" : "+l"(acc) : "l"(a), "l"(b));
}
__device__ __forceinline__ float2 unpk(unsigned long long a) {
    unsigned lo, hi;
    asm("mov.b64 {%0, %1}, %2;" : "=r"(lo), "=r"(hi) : "l"(a));
    return make_float2(__uint_as_float(lo), __uint_as_float(hi));
}

// ---------------- edge-index dtype detect + normalize --------------------------
// int64 indices in [0, NN): high 32-bit word of every element is 0.
// int32 indices: "high words" are other random indices, nonzero w.h.p.
__global__ void detect_kernel(const int* __restrict__ ei32) {
    int is64 = 1;
    #pragma unroll
    for (int i = 0; i < 64; i++)
        if (ei32[2 * i + 1] != 0) is64 = 0;
    g_is64 = is64;
}

__global__ void convert_kernel(const void* __restrict__ ei) {
    int e = blockIdx.x * blockDim.x + threadIdx.x;
    if (e >= EE) return;
    if (g_is64) {
        const long long* p = (const long long*)ei;
        g_dst[e] = (int)p[e];
        g_src[e] = (int)p[EE + e];
    } else {
        const int* p = (const int*)ei;
        g_dst[e] = p[e];
        g_src[e] = p[EE + e];
    }
}

// ---------------- GEMM: y[rows,128] = x[rows,128] @ W[128,128] + b -------------
// Block = 256 threads (8 warps), 4 rows per warp -> 32 rows/block.
// W in dynamic smem (64KB), x tile in static smem (16KB).
__global__ __launch_bounds__(256) void gemm128(const float* __restrict__ x,
                                               const float* __restrict__ W,
                                               const float* __restrict__ bias,
                                               float* __restrict__ y, int nrows) {
    extern __shared__ float sW[];          // 128*128 floats
    __shared__ float sX[32 * DD];          // 32 rows
    const int tid  = threadIdx.x;
    const int row0 = blockIdx.x * 32;

    // load W
    const float4* Wv = (const float4*)W;
    float4* sWv = (float4*)sW;
    #pragma unroll
    for (int i = 0; i < (DD * DD / 4) / 256; i++)
        sWv[i * 256 + tid] = Wv[i * 256 + tid];

    // load x tile (zero-pad tail rows)
    const int nrow_t = nrows - row0;
    float4* sXv = (float4*)sX;
    #pragma unroll
    for (int i = 0; i < (32 * DD / 4) / 256; i++) {
        int idx = i * 256 + tid;
        int r = idx >> 5;                  // 32 float4 per row
        float4 v = make_float4(0.f, 0.f, 0.f, 0.f);
        if (r < nrow_t) v = ((const float4*)(x + (size_t)(row0 + r) * DD))[idx & 31];
        sXv[idx] = v;
    }
    __syncthreads();

    const int warp = tid >> 5, lane = tid & 31;
    const int r0 = warp * 4;
    const float* xr = sX + r0 * DD;

    unsigned long long acc[4][2] = {};
    #pragma unroll 4
    for (int k4 = 0; k4 < DD / 4; k4++) {
        float4 xv[4];
        #pragma unroll
        for (int r = 0; r < 4; r++)
            xv[r] = ((const float4*)(xr + r * DD))[k4];   // broadcast read
        #pragma unroll
        for (int j = 0; j < 4; j++) {
            int k = k4 * 4 + j;
            ulonglong2 w2 = ((const ulonglong2*)(sW + k * DD))[lane];  // cols 4l..4l+3
            #pragma unroll
            for (int r = 0; r < 4; r++) {
                float xk = (j == 0) ? xv[r].x : (j == 1) ? xv[r].y
                         : (j == 2) ? xv[r].z : xv[r].w;
                unsigned long long p = pk2(xk);
                ffma2(acc[r][0], w2.x, p);
                ffma2(acc[r][1], w2.y, p);
            }
        }
    }

    float4 bv = ((const float4*)bias)[lane];
    #pragma unroll
    for (int r = 0; r < 4; r++) {
        int row = row0 + r0 + r;
        if (row < nrows) {
            float2 lo = unpk(acc[r][0]);
            float2 hi = unpk(acc[r][1]);
            float4 o = make_float4(lo.x + bv.x, lo.y + bv.y, hi.x + bv.z, hi.y + bv.w);
            ((float4*)(y + (size_t)row * DD))[lane] = o;
        }
    }
}

// ---------------- CSR build ----------------------------------------------------
__global__ void hist_kernel() {
    int e = blockIdx.x * blockDim.x + threadIdx.x;
    if (e < EE) atomicAdd(&g_deg[g_dst[e]], 1);
}

// Single-block 3-phase scan: thread t serially owns chunk [t*C, (t+1)*C);
// block-scan of 1024 thread totals (warp shfl + smem); serial write-out.
__global__ __launch_bounds__(1024) void scan_kernel() {
    __shared__ int warp_tot[32];
    const int t = threadIdx.x;
    const int C = (NN + 1023) / 1024;      // 49
    const int beg = t * C;
    const int end = (beg + C < NN) ? beg + C : NN;

    int tot = 0;
    for (int i = beg; i < end; i++) tot += g_deg[i];

    int lane = t & 31, warp = t >> 5;
    int v = tot;
    #pragma unroll
    for (int off = 1; off < 32; off <<= 1) {
        int n = __shfl_up_sync(0xffffffffu, v, off);
        if (lane >= off) v += n;
    }
    if (lane == 31) warp_tot[warp] = v;
    __syncthreads();
    if (warp == 0) {
        int wv = warp_tot[lane];
        #pragma unroll
        for (int off = 1; off < 32; off <<= 1) {
            int n = __shfl_up_sync(0xffffffffu, wv, off);
            if (lane >= off) wv += n;
        }
        warp_tot[lane] = wv;
    }
    __syncthreads();
    int excl = v - tot + (warp > 0 ? warp_tot[warp - 1] : 0);

    int run = excl;
    for (int i = beg; i < end; i++) {
        int d = g_deg[i];
        g_rowptr[i] = run;
        g_cursor[i] = run;
        run += d;
    }
    if (t == 1023) g_rowptr[NN] = run;
}

__global__ void scatter_kernel() {
    int e = blockIdx.x * blockDim.x + threadIdx.x;
    if (e < EE) {
        int pos = atomicAdd(&g_cursor[g_dst[e]], 1);
        g_eids[pos] = e;
    }
}

// ---------------- edge logits: warp per edge -----------------------------------
__global__ __launch_bounds__(256) void edge_kernel(const float* __restrict__ ab,
                                                   float* __restrict__ logits_out) {
    int widx = (int)((blockIdx.x * (unsigned)blockDim.x + threadIdx.x) >> 5);
    int lane = threadIdx.x & 31;
    if (widx >= EE) return;
    int dst = g_dst[widx];
    int src = g_src[widx];
    float4 q = ((const float4*)(g_q + (size_t)dst * DD))[lane];
    float4 k = ((const float4*)(g_k + (size_t)src * DD))[lane];
    float s = q.x * k.x + q.y * k.y + q.z * k.z + q.w * k.w;
    s += __shfl_xor_sync(0xffffffffu, s, 1);
    s += __shfl_xor_sync(0xffffffffu, s, 2);
    if ((lane & 3) == 0) {
        int h = lane >> 2;
        logits_out[(size_t)widx * HH + h] = 0.25f * s + ab[(size_t)widx * HH + h];
    }
}

// ---------------- per-node softmax + weighted V aggregation: warp per node -----
__global__ __launch_bounds__(256) void node_kernel(const float* __restrict__ logits,
                                                   float* __restrict__ agg) {
    int nidx = (int)((blockIdx.x * (unsigned)blockDim.x + threadIdx.x) >> 5);
    int lane = threadIdx.x & 31;
    if (nidx >= NN) return;
    int beg = g_rowptr[nidx], end = g_rowptr[nidx + 1];
    int h = lane >> 2;

    float m = -3.0e38f;
    for (int i = beg; i < end; i++) {
        int e = g_eids[i];
        m = fmaxf(m, logits[(size_t)e * HH + h]);
    }

    float4 acc = make_float4(0.f, 0.f, 0.f, 0.f);
    float sden = 0.f;
    for (int i = beg; i < end; i++) {
        int e = g_eids[i];
        float lv = logits[(size_t)e * HH + h];
        float ex = __expf(lv - m);
        sden += ex;
        int src = g_src[e];
        float4 v = ((const float4*)(g_v + (size_t)src * DD))[lane];
        acc.x += ex * v.x;
        acc.y += ex * v.y;
        acc.z += ex * v.z;
        acc.w += ex * v.w;
    }
    float inv = (end > beg) ? 1.0f / sden : 0.f;
    float4 o = make_float4(acc.x * inv, acc.y * inv, acc.z * inv, acc.w * inv);
    ((float4*)(agg + (size_t)nidx * DD))[lane] = o;
}

// ---------------- launch -------------------------------------------------------
extern "C" void kernel_launch(void* const* d_in, const int* in_sizes, int n_in,
                              void* d_out, int out_size) {
    const float* x  = (const float*)d_in[0];
    const void*  ei = d_in[1];
    const float* ab = (const float*)d_in[2];
    const float* Wq = (const float*)d_in[3]; const float* bq = (const float*)d_in[4];
    const float* Wk = (const float*)d_in[5]; const float* bk = (const float*)d_in[6];
    const float* Wv = (const float*)d_in[7]; const float* bv = (const float*)d_in[8];
    const float* Wo = (const float*)d_in[9]; const float* bo = (const float*)d_in[10];
    float* out = (float*)d_out;

    cudaFuncSetAttribute(gemm128, cudaFuncAttributeMaxDynamicSharedMemorySize, 65536);

    void* tmp;
    float *qp, *kp, *vp, *aggp, *logp; int* degp;
    cudaGetSymbolAddress(&tmp, g_q);      qp   = (float*)tmp;
    cudaGetSymbolAddress(&tmp, g_k);      kp   = (float*)tmp;
    cudaGetSymbolAddress(&tmp, g_v);      vp   = (float*)tmp;
    cudaGetSymbolAddress(&tmp, g_agg);    aggp = (float*)tmp;
    cudaGetSymbolAddress(&tmp, g_logits); logp = (float*)tmp;
    cudaGetSymbolAddress(&tmp, g_deg);    degp = (int*)tmp;

    // output layout: [N*D out][E*H logits] (tuple flattened). Fall back to
    // scratch for logits if the harness buffer only holds `out`.
    float* logits_out = ((size_t)out_size >= (size_t)NN * DD + (size_t)EE * HH)
                            ? out + (size_t)NN * DD
                            : logp;

    const int gemm_blocks = (NN + 31) / 32;   // 1563

    detect_kernel<<<1, 1>>>((const int*)ei);
    convert_kernel<<<(EE + 255) / 256, 256>>>(ei);

    gemm128<<<gemm_blocks, 256, 65536>>>(x, Wq, bq, qp, NN);
    gemm128<<<gemm_blocks, 256, 65536>>>(x, Wk, bk, kp, NN);
    gemm128<<<gemm_blocks, 256, 65536>>>(x, Wv, bv, vp, NN);

    cudaMemsetAsync(degp, 0, NN * sizeof(int));
    hist_kernel<<<EE / 256, 256>>>();
    scan_kernel<<<1, 1024>>>();
    scatter_kernel<<<EE / 256, 256>>>();

    edge_kernel<<<EE / 8, 256>>>(ab, logits_out);
    node_kernel<<<NN / 8, 256>>>(logits_out, aggp);

    gemm128<<<gemm_blocks, 256, 65536>>>(aggp, Wo, bo, out, NN);
}

// round 10
// speedup vs baseline: 1.1497x; 1.1497x over previous
#include <cuda_runtime.h>
#include <cstdint>

#define NN 50000
#define EE 800000
#define DD 128
#define HH 8

// ---------------- scratch (static __device__ arrays; no allocation) ------------
__device__ float g_q[(size_t)NN * DD];
__device__ float g_k[(size_t)NN * DD];
__device__ float g_v[(size_t)NN * DD];
__device__ float g_agg[(size_t)NN * DD];
__device__ float g_logits[(size_t)EE * HH];   // fallback if out buffer lacks logits room
__device__ int   g_dst[EE];
__device__ int   g_src[EE];
__device__ int   g_deg[NN];
__device__ int   g_rowptr[NN + 1];
__device__ int   g_cursor[NN];
__device__ int   g_eids[EE];
__device__ int   g_is64;

// ---------------- f32x2 helpers (FFMA2 only reachable via PTX) -----------------
__device__ __forceinline__ unsigned long long pk2(float v) {
    unsigned u = __float_as_uint(v);
    unsigned long long p;
    asm("mov.b64 %0, {%1, %1};" : "=l"(p) : "r"(u));
    return p;
}
__device__ __forceinline__ void ffma2(unsigned long long& acc, unsigned long long a,
                                      unsigned long long b) {
    asm("fma.rn.f32x2 %0, %1, %2, %0;" : "+l"(acc) : "l"(a), "l"(b));
}
__device__ __forceinline__ float2 unpk(unsigned long long a) {
    unsigned lo, hi;
    asm("mov.b64 {%0, %1}, %2;" : "=r"(lo), "=r"(hi) : "l"(a));
    return make_float2(__uint_as_float(lo), __uint_as_float(hi));
}

// ---------------- edge-index dtype detect + normalize + degree histogram -------
__global__ void detect_kernel(const int* __restrict__ ei32) {
    int is64 = 1;
    #pragma unroll
    for (int i = 0; i < 64; i++)
        if (ei32[2 * i + 1] != 0) is64 = 0;
    g_is64 = is64;
}

__global__ void convert_kernel(const void* __restrict__ ei) {
    int e = blockIdx.x * blockDim.x + threadIdx.x;
    if (e >= EE) return;
    int d, s;
    if (g_is64) {
        const long long* p = (const long long*)ei;
        d = (int)p[e];
        s = (int)p[EE + e];
    } else {
        const int* p = (const int*)ei;
        d = p[e];
        s = p[EE + e];
    }
    g_dst[e] = d;
    g_src[e] = s;
    atomicAdd(&g_deg[d], 1);
}

// ---------------- GEMM: y[rows,128] = x[rows,128] @ W[128,128] + b -------------
// Block = 256 threads (8 warps), 8 rows per warp -> 64 rows/block.
// W in dynamic smem (64KB), x tile in static smem (32KB).
__global__ __launch_bounds__(256) void gemm128(const float* __restrict__ x,
                                               const float* __restrict__ W,
                                               const float* __restrict__ bias,
                                               float* __restrict__ y, int nrows) {
    extern __shared__ float sW[];          // 128*128 floats
    __shared__ float sX[64 * DD];          // 64 rows
    const int tid  = threadIdx.x;
    const int row0 = blockIdx.x * 64;

    // load W
    const float4* Wv = (const float4*)W;
    float4* sWv = (float4*)sW;
    #pragma unroll
    for (int i = 0; i < (DD * DD / 4) / 256; i++)
        sWv[i * 256 + tid] = Wv[i * 256 + tid];

    // load x tile (zero-pad tail rows)
    const int nrow_t = nrows - row0;
    float4* sXv = (float4*)sX;
    #pragma unroll
    for (int i = 0; i < (64 * DD / 4) / 256; i++) {
        int idx = i * 256 + tid;
        int r = idx >> 5;                  // 32 float4 per row
        float4 v = make_float4(0.f, 0.f, 0.f, 0.f);
        if (r < nrow_t) v = ((const float4*)(x + (size_t)(row0 + r) * DD))[idx & 31];
        sXv[idx] = v;
    }
    __syncthreads();

    const int warp = tid >> 5, lane = tid & 31;
    const int r0 = warp * 8;

    unsigned long long acc[8][2] = {};
    #pragma unroll 2
    for (int k4 = 0; k4 < DD / 4; k4++) {
        float4 xv[8];
        #pragma unroll
        for (int r = 0; r < 8; r++)
            xv[r] = sXv[(r0 + r) * 32 + k4];               // broadcast read
        #pragma unroll
        for (int j = 0; j < 4; j++) {
            int k = k4 * 4 + j;
            ulonglong2 w2 = ((const ulonglong2*)(sW + k * DD))[lane];  // cols 4l..4l+3
            #pragma unroll
            for (int r = 0; r < 8; r++) {
                float xk = (j == 0) ? xv[r].x : (j == 1) ? xv[r].y
                         : (j == 2) ? xv[r].z : xv[r].w;
                unsigned long long p = pk2(xk);
                ffma2(acc[r][0], w2.x, p);
                ffma2(acc[r][1], w2.y, p);
            }
        }
    }

    float4 bv = ((const float4*)bias)[lane];
    #pragma unroll
    for (int r = 0; r < 8; r++) {
        int row = row0 + r0 + r;
        if (row < nrows) {
            float2 lo = unpk(acc[r][0]);
            float2 hi = unpk(acc[r][1]);
            float4 o = make_float4(lo.x + bv.x, lo.y + bv.y, hi.x + bv.z, hi.y + bv.w);
            ((float4*)(y + (size_t)row * DD))[lane] = o;
        }
    }
}

// ---------------- CSR build ----------------------------------------------------
// Single-block 3-phase scan: thread t serially owns chunk [t*C, (t+1)*C);
// block-scan of 1024 thread totals (warp shfl + smem); serial write-out.
__global__ __launch_bounds__(1024) void scan_kernel() {
    __shared__ int warp_tot[32];
    const int t = threadIdx.x;
    const int C = (NN + 1023) / 1024;      // 49
    const int beg = t * C;
    const int end = (beg + C < NN) ? beg + C : NN;

    int tot = 0;
    for (int i = beg; i < end; i++) tot += g_deg[i];

    int lane = t & 31, warp = t >> 5;
    int v = tot;
    #pragma unroll
    for (int off = 1; off < 32; off <<= 1) {
        int n = __shfl_up_sync(0xffffffffu, v, off);
        if (lane >= off) v += n;
    }
    if (lane == 31) warp_tot[warp] = v;
    __syncthreads();
    if (warp == 0) {
        int wv = warp_tot[lane];
        #pragma unroll
        for (int off = 1; off < 32; off <<= 1) {
            int n = __shfl_up_sync(0xffffffffu, wv, off);
            if (lane >= off) wv += n;
        }
        warp_tot[lane] = wv;
    }
    __syncthreads();
    int excl = v - tot + (warp > 0 ? warp_tot[warp - 1] : 0);

    int run = excl;
    for (int i = beg; i < end; i++) {
        int d = g_deg[i];
        g_rowptr[i] = run;
        g_cursor[i] = run;
        run += d;
    }
    if (t == 1023) g_rowptr[NN] = run;
}

__global__ void scatter_kernel() {
    int e = blockIdx.x * blockDim.x + threadIdx.x;
    if (e < EE) {
        int pos = atomicAdd(&g_cursor[g_dst[e]], 1);
        g_eids[pos] = e;
    }
}

// ---------------- fused per-node: logits + online softmax + V aggregation ------
// Warp per node. Q row loaded ONCE into registers; stream CSR edge list:
// gather K row -> logit (write: output) -> online-softmax rescale of sum/acc
// with gathered V row. Eliminates the separate edge pass and logit re-reads.
__global__ __launch_bounds__(256) void node_fused_kernel(const float* __restrict__ ab,
                                                         float* __restrict__ logits_out,
                                                         float* __restrict__ agg) {
    int nidx = (int)((blockIdx.x * (unsigned)blockDim.x + threadIdx.x) >> 5);
    int lane = threadIdx.x & 31;
    if (nidx >= NN) return;
    const int beg = g_rowptr[nidx], end = g_rowptr[nidx + 1];
    const int h = lane >> 2;

    const float4 q = ((const float4*)(g_q + (size_t)nidx * DD))[lane];

    float m = -3.0e38f;
    float sden = 0.f;
    float4 acc = make_float4(0.f, 0.f, 0.f, 0.f);

    for (int i = beg; i < end; i++) {
        const int e = g_eids[i];
        const int src = g_src[e];
        const float4 k = ((const float4*)(g_k + (size_t)src * DD))[lane];
        const float4 v = ((const float4*)(g_v + (size_t)src * DD))[lane];

        float s = q.x * k.x + q.y * k.y + q.z * k.z + q.w * k.w;
        s += __shfl_xor_sync(0xffffffffu, s, 1);
        s += __shfl_xor_sync(0xffffffffu, s, 2);      // all 4 lanes of head h hold s

        const float logit = 0.25f * s + ab[(size_t)e * HH + h];
        if ((lane & 3) == 0)
            logits_out[(size_t)e * HH + h] = logit;

        const float newm = fmaxf(m, logit);
        const float scale = __expf(m - newm);         // 1.0 when max unchanged
        const float ex = __expf(logit - newm);
        sden = sden * scale + ex;
        acc.x = acc.x * scale + ex * v.x;
        acc.y = acc.y * scale + ex * v.y;
        acc.z = acc.z * scale + ex * v.z;
        acc.w = acc.w * scale + ex * v.w;
        m = newm;
    }

    const float inv = (end > beg) ? 1.0f / sden : 0.f;
    const float4 o = make_float4(acc.x * inv, acc.y * inv, acc.z * inv, acc.w * inv);
    ((float4*)(agg + (size_t)nidx * DD))[lane] = o;
}

// ---------------- launch -------------------------------------------------------
extern "C" void kernel_launch(void* const* d_in, const int* in_sizes, int n_in,
                              void* d_out, int out_size) {
    const float* x  = (const float*)d_in[0];
    const void*  ei = d_in[1];
    const float* ab = (const float*)d_in[2];
    const float* Wq = (const float*)d_in[3]; const float* bq = (const float*)d_in[4];
    const float* Wk = (const float*)d_in[5]; const float* bk = (const float*)d_in[6];
    const float* Wv = (const float*)d_in[7]; const float* bv = (const float*)d_in[8];
    const float* Wo = (const float*)d_in[9]; const float* bo = (const float*)d_in[10];
    float* out = (float*)d_out;

    cudaFuncSetAttribute(gemm128, cudaFuncAttributeMaxDynamicSharedMemorySize, 65536);

    void* tmp;
    float *qp, *kp, *vp, *aggp, *logp; int* degp;
    cudaGetSymbolAddress(&tmp, g_q);      qp   = (float*)tmp;
    cudaGetSymbolAddress(&tmp, g_k);      kp   = (float*)tmp;
    cudaGetSymbolAddress(&tmp, g_v);      vp   = (float*)tmp;
    cudaGetSymbolAddress(&tmp, g_agg);    aggp = (float*)tmp;
    cudaGetSymbolAddress(&tmp, g_logits); logp = (float*)tmp;
    cudaGetSymbolAddress(&tmp, g_deg);    degp = (int*)tmp;

    // output layout: [N*D out][E*H logits] (tuple flattened). Fall back to
    // scratch for logits if the harness buffer only holds `out`.
    float* logits_out = ((size_t)out_size >= (size_t)NN * DD + (size_t)EE * HH)
                            ? out + (size_t)NN * DD
                            : logp;

    const int gemm_blocks = (NN + 63) / 64;   // 782

    cudaMemsetAsync(degp, 0, NN * sizeof(int));
    detect_kernel<<<1, 1>>>((const int*)ei);
    convert_kernel<<<(EE + 255) / 256, 256>>>(ei);

    gemm128<<<gemm_blocks, 256, 65536>>>(x, Wq, bq, qp, NN);
    gemm128<<<gemm_blocks, 256, 65536>>>(x, Wk, bk, kp, NN);
    gemm128<<<gemm_blocks, 256, 65536>>>(x, Wv, bv, vp, NN);

    scan_kernel<<<1, 1024>>>();
    scatter_kernel<<<EE / 256, 256>>>();

    node_fused_kernel<<<(NN + 7) / 8, 256>>>(ab, logits_out, aggp);

    gemm128<<<gemm_blocks, 256, 65536>>>(aggp, Wo, bo, out, NN);
}